// round 8
// baseline (speedup 1.0000x reference)
#include <cuda_runtime.h>

#define NN 100000
#define NE 1600000
#define FULL 0xffffffffu

typedef unsigned long long u64;

#define FMA_F32X2(d, a, b, c) \
    asm("fma.rn.f32x2 %0, %1, %2, %3;" : "=l"(d) : "l"(a), "l"(b), "l"(c))
#define PACK_DUP_F32X2(d, x) \
    asm("mov.b64 %0, {%1, %1};" : "=l"(d) : "f"(x))
#define UNPACK_F32X2(lo, hi, in) \
    asm("mov.b64 {%0, %1}, %2;" : "=f"(lo), "=f"(hi) : "l"(in))

// ---------------- scratch ----------------
__device__ int   g_cnt[NN];
__device__ int   g_roff[NN + 1];
__device__ int   g_woff[NN + 1];
__device__ int   g_csrc[NE];
__device__ int   g_bsum[128];
__device__ float g_dinv[NN];
__device__ float g_as[NN * 4];
__device__ float g_ad[NN * 4];
__device__ float g_t0[NN * 64];
__device__ float g_ha[NN * 64];
__device__ float g_hb[NN * 64];

// ---------------- CSR build ----------------
__global__ void deg_kernel(const int* __restrict__ dst, int e) {
    int i = blockIdx.x * blockDim.x + threadIdx.x;
    if (i < e) atomicAdd(&g_cnt[dst[i]], 1);
}

__global__ void scan1_kernel(int n) {
    __shared__ int wsum[32];
    int i = blockIdx.x * 1024 + threadIdx.x;
    int lane = threadIdx.x & 31, wid = threadIdx.x >> 5;
    int v = (i < n) ? g_cnt[i] : 0;
    if (i < n) g_dinv[i] = rsqrtf((float)(v + 1));
    int s = v;
#pragma unroll
    for (int o = 1; o < 32; o <<= 1) {
        int t = __shfl_up_sync(FULL, s, o);
        if (lane >= o) s += t;
    }
    if (lane == 31) wsum[wid] = s;
    __syncthreads();
    if (wid == 0) {
        int ws = wsum[lane];
#pragma unroll
        for (int o = 1; o < 32; o <<= 1) {
            int t = __shfl_up_sync(FULL, ws, o);
            if (lane >= o) ws += t;
        }
        wsum[lane] = ws;
    }
    __syncthreads();
    if (wid > 0) s += wsum[wid - 1];
    if (i < n) g_roff[i + 1] = s;
    if (i == 0) g_roff[0] = 0;
    if (threadIdx.x == 1023) g_bsum[blockIdx.x] = s;
}

__global__ void scan2_kernel(int nb) {
    __shared__ int wsum[4];
    int lane = threadIdx.x & 31, wid = threadIdx.x >> 5;
    int v = (threadIdx.x < nb) ? g_bsum[threadIdx.x] : 0;
    int s = v;
#pragma unroll
    for (int o = 1; o < 32; o <<= 1) {
        int t = __shfl_up_sync(FULL, s, o);
        if (lane >= o) s += t;
    }
    if (lane == 31) wsum[wid] = s;
    __syncthreads();
    int add = 0;
    for (int w = 0; w < wid; w++) add += wsum[w];
    s += add;
    if (threadIdx.x < nb) g_bsum[threadIdx.x] = s;
}

__global__ void scan3_kernel(int n) {
    int i = blockIdx.x * 1024 + threadIdx.x;
    if (i < n) {
        int add = (blockIdx.x > 0) ? g_bsum[blockIdx.x - 1] : 0;
        int val = g_roff[i + 1] + add;
        g_roff[i + 1] = val;
        g_woff[i + 1] = val;
        if (i == 0) g_woff[0] = 0;
    }
}

__global__ void fill_kernel(const int* __restrict__ src, const int* __restrict__ dst, int e) {
    int i = blockIdx.x * blockDim.x + threadIdx.x;
    if (i < e) {
        int d = dst[i];
        int p = atomicAdd(&g_woff[d], 1);
        g_csrc[p] = src[i];
    }
}

// ---------------- dense matmul with packed fp32x2 FMA ----------------
// MODE: 1 = prescale rows by g_dinv (GCN), 2 = GAT att epilogue
template <int IN, int OUT, int MODE>
__global__ void __launch_bounds__(128) mm_kernel(const float* __restrict__ X,
                                                 const float* __restrict__ W,
                                                 float* __restrict__ Y, int n,
                                                 const float* __restrict__ ats,
                                                 const float* __restrict__ atd) {
    constexpr int TPR = OUT / 4;        // threads per row (each does 4 cols = 2 f32x2)
    constexpr int NR  = 128 / TPR;
    constexpr int RPB = NR * 2;         // 2 rows / thread
    __shared__ __align__(16) float Ws[IN * OUT];
    __shared__ __align__(16) float Xs[RPB * IN];

    for (int i = threadIdx.x; i < IN * OUT / 4; i += 128)
        ((float4*)Ws)[i] = ((const float4*)W)[i];

    int row0 = blockIdx.x * RPB;
    for (int i = threadIdx.x; i < RPB * IN / 4; i += 128) {
        int r = i / (IN / 4);
        int k4 = i % (IN / 4);
        int row = row0 + r;
        float4 val = make_float4(0.f, 0.f, 0.f, 0.f);
        if (row < n) val = ((const float4*)(X + (size_t)row * IN))[k4];
        ((float4*)Xs)[i] = val;
    }
    __syncthreads();

    int tr = threadIdx.x / TPR;
    int cg = threadIdx.x % TPR;
    int rA = 2 * tr, rB = 2 * tr + 1;

    u64 acc00 = 0, acc01 = 0, acc10 = 0, acc11 = 0;   // [row][colpair]
    const ulonglong2* Ws2 = (const ulonglong2*)Ws;    // packed pairs of W cols
#pragma unroll 16
    for (int k = 0; k < IN; k++) {
        float x0 = Xs[rA * IN + k];
        float x1 = Xs[rB * IN + k];
        ulonglong2 w = Ws2[k * TPR + cg];             // {w01, w23}
        u64 x0p, x1p;
        PACK_DUP_F32X2(x0p, x0);
        PACK_DUP_F32X2(x1p, x1);
        FMA_F32X2(acc00, w.x, x0p, acc00);
        FMA_F32X2(acc01, w.y, x0p, acc01);
        FMA_F32X2(acc10, w.x, x1p, acc10);
        FMA_F32X2(acc11, w.y, x1p, acc11);
    }

    float4 a0, a1;
    UNPACK_F32X2(a0.x, a0.y, acc00);
    UNPACK_F32X2(a0.z, a0.w, acc01);
    UNPACK_F32X2(a1.x, a1.y, acc10);
    UNPACK_F32X2(a1.z, a1.w, acc11);

    int rowA = row0 + rA, rowB = row0 + rB;
    if (MODE == 1) {
        if (rowA < n) {
            float s = g_dinv[rowA];
            a0.x *= s; a0.y *= s; a0.z *= s; a0.w *= s;
        }
        if (rowB < n) {
            float s = g_dinv[rowB];
            a1.x *= s; a1.y *= s; a1.z *= s; a1.w *= s;
        }
    }
    if (rowA < n) ((float4*)(Y + (size_t)rowA * OUT))[cg] = a0;
    if (rowB < n) ((float4*)(Y + (size_t)rowB * OUT))[cg] = a1;

    if (MODE == 2) {
        int head = cg >> 2;
        float4 av = ((const float4*)ats)[head * 4 + (cg & 3)];
        float4 dv = ((const float4*)atd)[head * 4 + (cg & 3)];
        float ps0 = a0.x * av.x + a0.y * av.y + a0.z * av.z + a0.w * av.w;
        float pd0 = a0.x * dv.x + a0.y * dv.y + a0.z * dv.z + a0.w * dv.w;
        float ps1 = a1.x * av.x + a1.y * av.y + a1.z * av.z + a1.w * av.w;
        float pd1 = a1.x * dv.x + a1.y * dv.y + a1.z * dv.z + a1.w * dv.w;
        ps0 += __shfl_down_sync(FULL, ps0, 2, 4); ps0 += __shfl_down_sync(FULL, ps0, 1, 4);
        pd0 += __shfl_down_sync(FULL, pd0, 2, 4); pd0 += __shfl_down_sync(FULL, pd0, 1, 4);
        ps1 += __shfl_down_sync(FULL, ps1, 2, 4); ps1 += __shfl_down_sync(FULL, ps1, 1, 4);
        pd1 += __shfl_down_sync(FULL, pd1, 2, 4); pd1 += __shfl_down_sync(FULL, pd1, 1, 4);
        if ((cg & 3) == 0) {
            if (rowA < n) { g_as[rowA * 4 + head] = ps0; g_ad[rowA * 4 + head] = pd0; }
            if (rowB < n) { g_as[rowB * 4 + head] = ps1; g_ad[rowB * 4 + head] = pd1; }
        }
    }
}

// ---------------- GCN aggregation (input pre-scaled by dinv[u]), MLP-4 loop ----------------
__global__ void __launch_bounds__(256) gcn_agg32(const float* __restrict__ h,
                                                 const float* __restrict__ bias,
                                                 float* __restrict__ out, int n) {
    int v = (blockIdx.x * blockDim.x + threadIdx.x) >> 5;
    int lane = threadIdx.x & 31;
    if (v >= n) return;
    float dv = g_dinv[v];
    float acc = h[(size_t)v * 32 + lane];
    int e0 = g_roff[v], e1 = g_roff[v + 1];
    int e = e0;
    for (; e + 4 <= e1; e += 4) {
        int u0 = g_csrc[e], u1 = g_csrc[e + 1], u2 = g_csrc[e + 2], u3 = g_csrc[e + 3];
        float p0 = h[(size_t)u0 * 32 + lane];
        float p1 = h[(size_t)u1 * 32 + lane];
        float p2 = h[(size_t)u2 * 32 + lane];
        float p3 = h[(size_t)u3 * 32 + lane];
        acc += (p0 + p1) + (p2 + p3);
    }
    for (; e < e1; e++) acc += h[(size_t)g_csrc[e] * 32 + lane];
    out[(size_t)v * 32 + lane] = fmaxf(dv * acc + bias[lane], 0.f);
}

__global__ void __launch_bounds__(256) gcn_agg64(const float* __restrict__ h,
                                                 const float* __restrict__ bias,
                                                 const float* __restrict__ res,
                                                 float* __restrict__ out, int n) {
    int v = (blockIdx.x * blockDim.x + threadIdx.x) >> 5;
    int lane = threadIdx.x & 31;
    if (v >= n) return;
    const float2* h2 = (const float2*)h;
    float dv = g_dinv[v];
    float2 acc = h2[(size_t)v * 32 + lane];
    int e0 = g_roff[v], e1 = g_roff[v + 1];
    int e = e0;
    for (; e + 4 <= e1; e += 4) {
        int u0 = g_csrc[e], u1 = g_csrc[e + 1], u2 = g_csrc[e + 2], u3 = g_csrc[e + 3];
        float2 p0 = h2[(size_t)u0 * 32 + lane];
        float2 p1 = h2[(size_t)u1 * 32 + lane];
        float2 p2 = h2[(size_t)u2 * 32 + lane];
        float2 p3 = h2[(size_t)u3 * 32 + lane];
        acc.x += (p0.x + p1.x) + (p2.x + p3.x);
        acc.y += (p0.y + p1.y) + (p2.y + p3.y);
    }
    for (; e < e1; e++) {
        float2 p = h2[(size_t)g_csrc[e] * 32 + lane];
        acc.x += p.x; acc.y += p.y;
    }
    float2 b2 = ((const float2*)bias)[lane];
    float2 o;
    o.x = fmaxf(dv * acc.x + b2.x, 0.f);
    o.y = fmaxf(dv * acc.y + b2.y, 0.f);
    if (res) {
        float2 r2 = ((const float2*)res)[(size_t)v * 32 + lane];
        o.x += r2.x; o.y += r2.y;
    }
    ((float2*)out)[(size_t)v * 32 + lane] = o;
}

// ---------------- GAT ----------------
__device__ __forceinline__ float leakyr(float x) { return x > 0.f ? x : 0.2f * x; }
__device__ __forceinline__ float sel4(float4 v, int h) {
    float a = (h & 1) ? v.y : v.x;
    float b = (h & 1) ? v.w : v.z;
    return (h & 2) ? b : a;
}

template <bool FINAL>
__global__ void __launch_bounds__(256) gat_agg(const float* __restrict__ hg,
                                               const float* __restrict__ bias,
                                               float* __restrict__ out,
                                               const float* __restrict__ Wl,
                                               const float* __restrict__ bl, int n) {
    int v = (blockIdx.x * blockDim.x + threadIdx.x) >> 5;
    int lane = threadIdx.x & 31;
    if (v >= n) return;
    int hh = lane >> 3;
    const float2* h2 = (const float2*)hg;
    const float4* as4 = (const float4*)g_as;
    const float4* ad4p = (const float4*)g_ad;

    float4 asv = as4[v];
    float4 adv = ad4p[v];
    int e0 = g_roff[v], e1 = g_roff[v + 1];

    // pass 1: per-head max, lane-parallel
    float4 m4;
    m4.x = leakyr(asv.x + adv.x);
    m4.y = leakyr(asv.y + adv.y);
    m4.z = leakyr(asv.z + adv.z);
    m4.w = leakyr(asv.w + adv.w);
    for (int e = e0 + lane; e < e1; e += 32) {
        int u = g_csrc[e];
        float4 au = as4[u];
        m4.x = fmaxf(m4.x, leakyr(au.x + adv.x));
        m4.y = fmaxf(m4.y, leakyr(au.y + adv.y));
        m4.z = fmaxf(m4.z, leakyr(au.z + adv.z));
        m4.w = fmaxf(m4.w, leakyr(au.w + adv.w));
    }
#pragma unroll
    for (int o = 16; o; o >>= 1) {
        m4.x = fmaxf(m4.x, __shfl_xor_sync(FULL, m4.x, o));
        m4.y = fmaxf(m4.y, __shfl_xor_sync(FULL, m4.y, o));
        m4.z = fmaxf(m4.z, __shfl_xor_sync(FULL, m4.z, o));
        m4.w = fmaxf(m4.w, __shfl_xor_sync(FULL, m4.w, o));
    }
    float mx = sel4(m4, hh);
    float advh = sel4(adv, hh);

    // pass 2: exp + weighted accumulate, unroll 2 for MLP
    float pself = __expf(leakyr(sel4(asv, hh) + advh) - mx);
    float2 hv = h2[(size_t)v * 32 + lane];
    float2 acc; acc.x = pself * hv.x; acc.y = pself * hv.y;
    float den = pself;
    int e = e0;
    for (; e + 2 <= e1; e += 2) {
        int u0 = g_csrc[e], u1 = g_csrc[e + 1];
        float4 au0 = as4[u0];
        float4 au1 = as4[u1];
        float2 f0 = h2[(size_t)u0 * 32 + lane];
        float2 f1 = h2[(size_t)u1 * 32 + lane];
        float p0 = __expf(leakyr(sel4(au0, hh) + advh) - mx);
        float p1 = __expf(leakyr(sel4(au1, hh) + advh) - mx);
        acc.x += p0 * f0.x + p1 * f1.x;
        acc.y += p0 * f0.y + p1 * f1.y;
        den += p0 + p1;
    }
    for (; e < e1; e++) {
        int u = g_csrc[e];
        float4 au = as4[u];
        float p = __expf(leakyr(sel4(au, hh) + advh) - mx);
        float2 fu = h2[(size_t)u * 32 + lane];
        acc.x += p * fu.x; acc.y += p * fu.y;
        den += p;
    }
    float inv = 1.f / den;
    float2 b2 = ((const float2*)bias)[lane];
    float2 o;
    o.x = fmaxf(acc.x * inv + b2.x, 0.f);
    o.y = fmaxf(acc.y * inv + b2.y, 0.f);

    if (FINAL) {
        float2 wl = ((const float2*)Wl)[lane];
        float p = o.x * wl.x + o.y * wl.y;
#pragma unroll
        for (int s = 16; s; s >>= 1) p += __shfl_xor_sync(FULL, p, s);
        if (lane == 0) out[v] = fmaxf(p + bl[0], 0.f);
    } else {
        ((float2*)out)[(size_t)v * 32 + lane] = o;
    }
}

// ---------------- launch ----------------
extern "C" void kernel_launch(void* const* d_in, const int* in_sizes, int n_in,
                              void* d_out, int out_size) {
    const float* x   = (const float*)d_in[0];
    const int*   ei  = (const int*)d_in[1];
    const float* W1  = (const float*)d_in[2];
    const float* b1  = (const float*)d_in[3];
    const float* W2  = (const float*)d_in[4];
    const float* b2  = (const float*)d_in[5];
    const float* W3  = (const float*)d_in[6];
    const float* b3  = (const float*)d_in[7];
    const float* Wg  = (const float*)d_in[8];
    const float* ats = (const float*)d_in[9];
    const float* atd = (const float*)d_in[10];
    const float* bg  = (const float*)d_in[11];
    const float* Wl  = (const float*)d_in[12];
    const float* bl  = (const float*)d_in[13];
    float* out = (float*)d_out;

    int n = in_sizes[0] / 128;
    int e = in_sizes[1] / 2;
    const int* src = ei;
    const int* dst = ei + e;

    void* p;
    int* cnt_ptr; cudaGetSymbolAddress(&p, g_cnt); cnt_ptr = (int*)p;
    float *t0, *ha, *hb;
    cudaGetSymbolAddress(&p, g_t0); t0 = (float*)p;
    cudaGetSymbolAddress(&p, g_ha); ha = (float*)p;
    cudaGetSymbolAddress(&p, g_hb); hb = (float*)p;

    int nb = (n + 1023) / 1024;
    int gE = (e + 255) / 256;
    int gW = (n * 32 + 255) / 256;

    cudaMemsetAsync(cnt_ptr, 0, sizeof(int) * NN, 0);
    deg_kernel<<<gE, 256>>>(dst, e);
    scan1_kernel<<<nb, 1024>>>(n);
    scan2_kernel<<<1, 128>>>(nb);
    scan3_kernel<<<nb, 1024>>>(n);
    fill_kernel<<<gE, 256>>>(src, dst, e);

    mm_kernel<128, 32, 1><<<(n + 31) / 32, 128>>>(x, W1, t0, n, nullptr, nullptr);
    gcn_agg32<<<gW, 256>>>(t0, b1, ha, n);

    mm_kernel<32, 64, 1><<<(n + 15) / 16, 128>>>(ha, W2, t0, n, nullptr, nullptr);
    gcn_agg64<<<gW, 256>>>(t0, b2, nullptr, hb, n);

    mm_kernel<64, 64, 2><<<(n + 15) / 16, 128>>>(hb, Wg, t0, n, ats, atd);
    gat_agg<false><<<gW, 256>>>(t0, bg, ha, nullptr, nullptr, n);

    mm_kernel<64, 64, 1><<<(n + 15) / 16, 128>>>(ha, W3, t0, n, nullptr, nullptr);
    gcn_agg64<<<gW, 256>>>(t0, b3, ha, hb, n);

    mm_kernel<64, 64, 2><<<(n + 15) / 16, 128>>>(hb, Wg, t0, n, ats, atd);
    gat_agg<true><<<gW, 256>>>(t0, bg, out, Wl, bl, n);
}

// round 12
// speedup vs baseline: 1.0593x; 1.0593x over previous
#include <cuda_runtime.h>
#include <cuda_fp16.h>

#define NN 100000
#define NE 1600000
#define FULL 0xffffffffu

typedef unsigned long long u64;

#define FMA_F32X2(d, a, b, c) \
    asm("fma.rn.f32x2 %0, %1, %2, %3;" : "=l"(d) : "l"(a), "l"(b), "l"(c))
#define PACK_DUP_F32X2(d, x) \
    asm("mov.b64 %0, {%1, %1};" : "=l"(d) : "f"(x))
#define UNPACK_F32X2(lo, hi, in) \
    asm("mov.b64 {%0, %1}, %2;" : "=f"(lo), "=f"(hi) : "l"(in))

// ---------------- scratch ----------------
__device__ int      g_cnt[NN];
__device__ int      g_roff[NN + 1];
__device__ int      g_woff[NN + 1];
__device__ int      g_csrc[NE];
__device__ int      g_bsum[128];
__device__ unsigned g_asmax[8];          // per-head global max of a_s, 2 GAT layers
__device__ float    g_dinv[NN];
__device__ float    g_as[NN * 4];
__device__ float    g_ad[NN * 4];
__device__ __half   g_t0h[NN * 64];      // pre-agg features (half)
__device__ __half   g_h1p[NN * 32];      // layer-1 output, dinv-prescaled (half)
__device__ float    g_z[NN * 32];        // layer-2 aggregated 32ch (fp32)
__device__ float    g_ha[NN * 64];
__device__ float    g_hb[NN * 64];

// ordered-float <-> unsigned encoding for atomicMax
__device__ __forceinline__ unsigned fenc(float f) {
    int i = __float_as_int(f);
    return (i >= 0) ? ((unsigned)i | 0x80000000u) : ~(unsigned)i;
}
__device__ __forceinline__ float fdec(unsigned k) {
    int i = (k & 0x80000000u) ? (int)(k & 0x7fffffffu) : ~(int)k;
    return __int_as_float(i);
}

// ---------------- CSR build ----------------
__global__ void deg_kernel(const int* __restrict__ dst, int e) {
    int i = blockIdx.x * blockDim.x + threadIdx.x;
    if (i < e) atomicAdd(&g_cnt[dst[i]], 1);
}

__global__ void scan1_kernel(int n) {
    __shared__ int wsum[32];
    int i = blockIdx.x * 1024 + threadIdx.x;
    int lane = threadIdx.x & 31, wid = threadIdx.x >> 5;
    int v = (i < n) ? g_cnt[i] : 0;
    if (i < n) g_dinv[i] = rsqrtf((float)(v + 1));
    int s = v;
#pragma unroll
    for (int o = 1; o < 32; o <<= 1) {
        int t = __shfl_up_sync(FULL, s, o);
        if (lane >= o) s += t;
    }
    if (lane == 31) wsum[wid] = s;
    __syncthreads();
    if (wid == 0) {
        int ws = wsum[lane];
#pragma unroll
        for (int o = 1; o < 32; o <<= 1) {
            int t = __shfl_up_sync(FULL, ws, o);
            if (lane >= o) ws += t;
        }
        wsum[lane] = ws;
    }
    __syncthreads();
    if (wid > 0) s += wsum[wid - 1];
    if (i < n) g_roff[i + 1] = s;
    if (i == 0) g_roff[0] = 0;
    if (threadIdx.x == 1023) g_bsum[blockIdx.x] = s;
}

__global__ void scan2_kernel(int nb) {
    __shared__ int wsum[4];
    int lane = threadIdx.x & 31, wid = threadIdx.x >> 5;
    int v = (threadIdx.x < nb) ? g_bsum[threadIdx.x] : 0;
    int s = v;
#pragma unroll
    for (int o = 1; o < 32; o <<= 1) {
        int t = __shfl_up_sync(FULL, s, o);
        if (lane >= o) s += t;
    }
    if (lane == 31) wsum[wid] = s;
    __syncthreads();
    int add = 0;
    for (int w = 0; w < wid; w++) add += wsum[w];
    s += add;
    if (threadIdx.x < nb) g_bsum[threadIdx.x] = s;
}

__global__ void scan3_kernel(int n) {
    int i = blockIdx.x * 1024 + threadIdx.x;
    if (blockIdx.x == 0 && threadIdx.x < 8) g_asmax[threadIdx.x] = 0u;  // reset GAT maxes
    if (i < n) {
        int add = (blockIdx.x > 0) ? g_bsum[blockIdx.x - 1] : 0;
        int val = g_roff[i + 1] + add;
        g_roff[i + 1] = val;
        g_woff[i + 1] = val;
        if (i == 0) g_woff[0] = 0;
    }
}

__global__ void fill_kernel(const int* __restrict__ src, const int* __restrict__ dst, int e) {
    int i = blockIdx.x * blockDim.x + threadIdx.x;
    if (i < e) {
        int d = dst[i];
        int p = atomicAdd(&g_woff[d], 1);
        g_csrc[p] = src[i];
    }
}

// ---------------- dense matmul (f32x2), 2 rows/thread ----------------
// MODE 1: prescale by g_dinv, write half     (GCN pre-agg)
// MODE 2: write half + a_s/a_d + global max  (GAT pre-agg)
// MODE 3: +bias, relu, write fp32            (layer-2 post-agg)
template <int IN, int OUT, int MODE>
__global__ void __launch_bounds__(128) mm_kernel(const float* __restrict__ X,
                                                 const float* __restrict__ W,
                                                 void* __restrict__ Yv, int n,
                                                 const float* __restrict__ ats,
                                                 const float* __restrict__ atd,
                                                 const float* __restrict__ bias,
                                                 int lbase) {
    constexpr int TPR = OUT / 4;
    constexpr int NR  = 128 / TPR;
    constexpr int RPB = NR * 2;
    __shared__ __align__(16) float Ws[IN * OUT];
    __shared__ __align__(16) float Xs[RPB * IN];
    __shared__ unsigned smax[4];

    for (int i = threadIdx.x; i < IN * OUT / 4; i += 128)
        ((float4*)Ws)[i] = ((const float4*)W)[i];
    if (MODE == 2 && threadIdx.x < 4) smax[threadIdx.x] = 0u;

    int row0 = blockIdx.x * RPB;
    for (int i = threadIdx.x; i < RPB * IN / 4; i += 128) {
        int r = i / (IN / 4);
        int k4 = i % (IN / 4);
        int row = row0 + r;
        float4 val = make_float4(0.f, 0.f, 0.f, 0.f);
        if (row < n) val = ((const float4*)(X + (size_t)row * IN))[k4];
        ((float4*)Xs)[i] = val;
    }
    __syncthreads();

    int tr = threadIdx.x / TPR;
    int cg = threadIdx.x % TPR;
    int rA = 2 * tr, rB = 2 * tr + 1;

    u64 acc00 = 0, acc01 = 0, acc10 = 0, acc11 = 0;
    const ulonglong2* Ws2 = (const ulonglong2*)Ws;
#pragma unroll 16
    for (int k = 0; k < IN; k++) {
        float x0 = Xs[rA * IN + k];
        float x1 = Xs[rB * IN + k];
        ulonglong2 w = Ws2[k * TPR + cg];
        u64 x0p, x1p;
        PACK_DUP_F32X2(x0p, x0);
        PACK_DUP_F32X2(x1p, x1);
        FMA_F32X2(acc00, w.x, x0p, acc00);
        FMA_F32X2(acc01, w.y, x0p, acc01);
        FMA_F32X2(acc10, w.x, x1p, acc10);
        FMA_F32X2(acc11, w.y, x1p, acc11);
    }

    float4 a0, a1;
    UNPACK_F32X2(a0.x, a0.y, acc00);
    UNPACK_F32X2(a0.z, a0.w, acc01);
    UNPACK_F32X2(a1.x, a1.y, acc10);
    UNPACK_F32X2(a1.z, a1.w, acc11);

    int rowA = row0 + rA, rowB = row0 + rB;

    if (MODE == 1) {
        if (rowA < n) {
            float s = g_dinv[rowA];
            a0.x *= s; a0.y *= s; a0.z *= s; a0.w *= s;
        }
        if (rowB < n) {
            float s = g_dinv[rowB];
            a1.x *= s; a1.y *= s; a1.z *= s; a1.w *= s;
        }
    }

    if (MODE == 1 || MODE == 2) {
        __half* Y = (__half*)Yv;
        if (rowA < n) {
            __half2 lo = __floats2half2_rn(a0.x, a0.y), hi = __floats2half2_rn(a0.z, a0.w);
            uint2 pk; pk.x = *(unsigned*)&lo; pk.y = *(unsigned*)&hi;
            *(uint2*)(Y + (size_t)rowA * OUT + cg * 4) = pk;
        }
        if (rowB < n) {
            __half2 lo = __floats2half2_rn(a1.x, a1.y), hi = __floats2half2_rn(a1.z, a1.w);
            uint2 pk; pk.x = *(unsigned*)&lo; pk.y = *(unsigned*)&hi;
            *(uint2*)(Y + (size_t)rowB * OUT + cg * 4) = pk;
        }
    } else {  // MODE 3
        float* Y = (float*)Yv;
        float4 b4 = ((const float4*)bias)[cg];
        a0.x = fmaxf(a0.x + b4.x, 0.f); a0.y = fmaxf(a0.y + b4.y, 0.f);
        a0.z = fmaxf(a0.z + b4.z, 0.f); a0.w = fmaxf(a0.w + b4.w, 0.f);
        a1.x = fmaxf(a1.x + b4.x, 0.f); a1.y = fmaxf(a1.y + b4.y, 0.f);
        a1.z = fmaxf(a1.z + b4.z, 0.f); a1.w = fmaxf(a1.w + b4.w, 0.f);
        if (rowA < n) ((float4*)(Y + (size_t)rowA * OUT))[cg] = a0;
        if (rowB < n) ((float4*)(Y + (size_t)rowB * OUT))[cg] = a1;
    }

    if (MODE == 2) {
        int head = cg >> 2;
        float4 av = ((const float4*)ats)[head * 4 + (cg & 3)];
        float4 dv = ((const float4*)atd)[head * 4 + (cg & 3)];
        float ps0 = a0.x * av.x + a0.y * av.y + a0.z * av.z + a0.w * av.w;
        float pd0 = a0.x * dv.x + a0.y * dv.y + a0.z * dv.z + a0.w * dv.w;
        float ps1 = a1.x * av.x + a1.y * av.y + a1.z * av.z + a1.w * av.w;
        float pd1 = a1.x * dv.x + a1.y * dv.y + a1.z * dv.z + a1.w * dv.w;
        ps0 += __shfl_down_sync(FULL, ps0, 2, 4); ps0 += __shfl_down_sync(FULL, ps0, 1, 4);
        pd0 += __shfl_down_sync(FULL, pd0, 2, 4); pd0 += __shfl_down_sync(FULL, pd0, 1, 4);
        ps1 += __shfl_down_sync(FULL, ps1, 2, 4); ps1 += __shfl_down_sync(FULL, ps1, 1, 4);
        pd1 += __shfl_down_sync(FULL, pd1, 2, 4); pd1 += __shfl_down_sync(FULL, pd1, 1, 4);
        if ((cg & 3) == 0) {
            if (rowA < n) {
                g_as[rowA * 4 + head] = ps0; g_ad[rowA * 4 + head] = pd0;
                atomicMax(&smax[head], fenc(ps0));
            }
            if (rowB < n) {
                g_as[rowB * 4 + head] = ps1; g_ad[rowB * 4 + head] = pd1;
                atomicMax(&smax[head], fenc(ps1));
            }
        }
        __syncthreads();
        if (threadIdx.x < 4) atomicMax(&g_asmax[lbase + threadIdx.x], smax[threadIdx.x]);
    }
}

// ---------------- layer-1 GCN agg: half in (prescaled), half out (prescaled) ----------------
__global__ void __launch_bounds__(256) gcn_agg32_L1(const __half* __restrict__ h,
                                                    const float* __restrict__ bias,
                                                    __half* __restrict__ out, int n) {
    int v = (blockIdx.x * blockDim.x + threadIdx.x) >> 5;
    int lane = threadIdx.x & 31;
    if (v >= n) return;
    float dv = g_dinv[v];
    float acc = __half2float(h[(size_t)v * 32 + lane]);
    int e0 = g_roff[v], e1 = g_roff[v + 1];
    int e = e0;
    for (; e + 4 <= e1; e += 4) {
        int u0 = g_csrc[e], u1 = g_csrc[e + 1], u2 = g_csrc[e + 2], u3 = g_csrc[e + 3];
        float p0 = __half2float(h[(size_t)u0 * 32 + lane]);
        float p1 = __half2float(h[(size_t)u1 * 32 + lane]);
        float p2 = __half2float(h[(size_t)u2 * 32 + lane]);
        float p3 = __half2float(h[(size_t)u3 * 32 + lane]);
        acc += (p0 + p1) + (p2 + p3);
    }
    for (; e < e1; e++) acc += __half2float(h[(size_t)g_csrc[e] * 32 + lane]);
    float o = fmaxf(dv * acc + bias[lane], 0.f);
    out[(size_t)v * 32 + lane] = __float2half(dv * o);   // prescale for next agg
}

// ---------------- layer-2 agg (before matmul): half in, fp32 out ----------------
__global__ void __launch_bounds__(256) agg32_L2(const __half* __restrict__ h,
                                                float* __restrict__ out, int n) {
    int v = (blockIdx.x * blockDim.x + threadIdx.x) >> 5;
    int lane = threadIdx.x & 31;
    if (v >= n) return;
    float dv = g_dinv[v];
    float acc = __half2float(h[(size_t)v * 32 + lane]);
    int e0 = g_roff[v], e1 = g_roff[v + 1];
    int e = e0;
    for (; e + 4 <= e1; e += 4) {
        int u0 = g_csrc[e], u1 = g_csrc[e + 1], u2 = g_csrc[e + 2], u3 = g_csrc[e + 3];
        float p0 = __half2float(h[(size_t)u0 * 32 + lane]);
        float p1 = __half2float(h[(size_t)u1 * 32 + lane]);
        float p2 = __half2float(h[(size_t)u2 * 32 + lane]);
        float p3 = __half2float(h[(size_t)u3 * 32 + lane]);
        acc += (p0 + p1) + (p2 + p3);
    }
    for (; e < e1; e++) acc += __half2float(h[(size_t)g_csrc[e] * 32 + lane]);
    out[(size_t)v * 32 + lane] = dv * acc;
}

// ---------------- GCN 64ch agg: half in (prescaled), fp32 out + residual ----------------
__global__ void __launch_bounds__(256) gcn_agg64h(const __half* __restrict__ h,
                                                  const float* __restrict__ bias,
                                                  const float* __restrict__ res,
                                                  float* __restrict__ out, int n) {
    int v = (blockIdx.x * blockDim.x + threadIdx.x) >> 5;
    int lane = threadIdx.x & 31;
    if (v >= n) return;
    const __half2* h2 = (const __half2*)h;
    float dv = g_dinv[v];
    float2 acc = __half22float2(h2[(size_t)v * 32 + lane]);
    int e0 = g_roff[v], e1 = g_roff[v + 1];
    int e = e0;
    for (; e + 4 <= e1; e += 4) {
        int u0 = g_csrc[e], u1 = g_csrc[e + 1], u2 = g_csrc[e + 2], u3 = g_csrc[e + 3];
        float2 p0 = __half22float2(h2[(size_t)u0 * 32 + lane]);
        float2 p1 = __half22float2(h2[(size_t)u1 * 32 + lane]);
        float2 p2 = __half22float2(h2[(size_t)u2 * 32 + lane]);
        float2 p3 = __half22float2(h2[(size_t)u3 * 32 + lane]);
        acc.x += (p0.x + p1.x) + (p2.x + p3.x);
        acc.y += (p0.y + p1.y) + (p2.y + p3.y);
    }
    for (; e < e1; e++) {
        float2 p = __half22float2(h2[(size_t)g_csrc[e] * 32 + lane]);
        acc.x += p.x; acc.y += p.y;
    }
    float2 b2 = ((const float2*)bias)[lane];
    float2 r2 = ((const float2*)res)[(size_t)v * 32 + lane];
    float2 o;
    o.x = fmaxf(dv * acc.x + b2.x, 0.f) + r2.x;
    o.y = fmaxf(dv * acc.y + b2.y, 0.f) + r2.y;
    ((float2*)out)[(size_t)v * 32 + lane] = o;
}

// ---------------- GAT ----------------
__device__ __forceinline__ float leakyr(float x) { return x > 0.f ? x : 0.2f * x; }
__device__ __forceinline__ float sel4(float4 v, int h) {
    float a = (h & 1) ? v.y : v.x;
    float b = (h & 1) ? v.w : v.z;
    return (h & 2) ? b : a;
}

template <bool FINAL>
__global__ void __launch_bounds__(256) gat_agg(const __half* __restrict__ hg,
                                               const float* __restrict__ bias,
                                               float* __restrict__ out,
                                               const float* __restrict__ Wl,
                                               const float* __restrict__ bl,
                                               int lbase, int n) {
    int v = (blockIdx.x * blockDim.x + threadIdx.x) >> 5;
    int lane = threadIdx.x & 31;
    if (v >= n) return;
    int hh = lane >> 3;
    const __half2* h2 = (const __half2*)hg;
    const float4* as4 = (const float4*)g_as;
    const float4* ad4p = (const float4*)g_ad;

    float4 asv = as4[v];
    float4 adv = ad4p[v];
    float advh = sel4(adv, hh);
    float mx = leakyr(fdec(g_asmax[lbase + hh]) + advh);   // global upper bound

    float pself = __expf(leakyr(sel4(asv, hh) + advh) - mx);
    float2 hv = __half22float2(h2[(size_t)v * 32 + lane]);
    float2 acc; acc.x = pself * hv.x; acc.y = pself * hv.y;
    float den = pself;

    int e0 = g_roff[v], e1 = g_roff[v + 1];
    int e = e0;
    for (; e + 4 <= e1; e += 4) {
        int u0 = g_csrc[e], u1 = g_csrc[e + 1], u2 = g_csrc[e + 2], u3 = g_csrc[e + 3];
        float4 au0 = as4[u0], au1 = as4[u1], au2 = as4[u2], au3 = as4[u3];
        float2 f0 = __half22float2(h2[(size_t)u0 * 32 + lane]);
        float2 f1 = __half22float2(h2[(size_t)u1 * 32 + lane]);
        float2 f2 = __half22float2(h2[(size_t)u2 * 32 + lane]);
        float2 f3 = __half22float2(h2[(size_t)u3 * 32 + lane]);
        float p0 = __expf(leakyr(sel4(au0, hh) + advh) - mx);
        float p1 = __expf(leakyr(sel4(au1, hh) + advh) - mx);
        float p2 = __expf(leakyr(sel4(au2, hh) + advh) - mx);
        float p3 = __expf(leakyr(sel4(au3, hh) + advh) - mx);
        acc.x += (p0 * f0.x + p1 * f1.x) + (p2 * f2.x + p3 * f3.x);
        acc.y += (p0 * f0.y + p1 * f1.y) + (p2 * f2.y + p3 * f3.y);
        den += (p0 + p1) + (p2 + p3);
    }
    for (; e < e1; e++) {
        int u = g_csrc[e];
        float4 au = as4[u];
        float p = __expf(leakyr(sel4(au, hh) + advh) - mx);
        float2 fu = __half22float2(h2[(size_t)u * 32 + lane]);
        acc.x += p * fu.x; acc.y += p * fu.y;
        den += p;
    }
    float inv = 1.f / den;
    float2 b2 = ((const float2*)bias)[lane];
    float2 o;
    o.x = fmaxf(acc.x * inv + b2.x, 0.f);
    o.y = fmaxf(acc.y * inv + b2.y, 0.f);

    if (FINAL) {
        float2 wl = ((const float2*)Wl)[lane];
        float p = o.x * wl.x + o.y * wl.y;
#pragma unroll
        for (int s = 16; s; s >>= 1) p += __shfl_xor_sync(FULL, p, s);
        if (lane == 0) out[v] = fmaxf(p + bl[0], 0.f);
    } else {
        ((float2*)out)[(size_t)v * 32 + lane] = o;
    }
}

// ---------------- launch ----------------
extern "C" void kernel_launch(void* const* d_in, const int* in_sizes, int n_in,
                              void* d_out, int out_size) {
    const float* x   = (const float*)d_in[0];
    const int*   ei  = (const int*)d_in[1];
    const float* W1  = (const float*)d_in[2];
    const float* b1  = (const float*)d_in[3];
    const float* W2  = (const float*)d_in[4];
    const float* b2  = (const float*)d_in[5];
    const float* W3  = (const float*)d_in[6];
    const float* b3  = (const float*)d_in[7];
    const float* Wg  = (const float*)d_in[8];
    const float* ats = (const float*)d_in[9];
    const float* atd = (const float*)d_in[10];
    const float* bg  = (const float*)d_in[11];
    const float* Wl  = (const float*)d_in[12];
    const float* bl  = (const float*)d_in[13];
    float* out = (float*)d_out;

    int n = in_sizes[0] / 128;
    int e = in_sizes[1] / 2;
    const int* src = ei;
    const int* dst = ei + e;

    void* p;
    int* cnt_ptr; cudaGetSymbolAddress(&p, g_cnt); cnt_ptr = (int*)p;
    __half *t0h, *h1p;
    float *z, *ha, *hb;
    cudaGetSymbolAddress(&p, g_t0h); t0h = (__half*)p;
    cudaGetSymbolAddress(&p, g_h1p); h1p = (__half*)p;
    cudaGetSymbolAddress(&p, g_z);   z   = (float*)p;
    cudaGetSymbolAddress(&p, g_ha);  ha  = (float*)p;
    cudaGetSymbolAddress(&p, g_hb);  hb  = (float*)p;

    int nb = (n + 1023) / 1024;
    int gE = (e + 255) / 256;
    int gW = (n * 32 + 255) / 256;

    // CSR build (also resets GAT global maxes in scan3)
    cudaMemsetAsync(cnt_ptr, 0, sizeof(int) * NN, 0);
    deg_kernel<<<gE, 256>>>(dst, e);
    scan1_kernel<<<nb, 1024>>>(n);
    scan2_kernel<<<1, 128>>>(nb);
    scan3_kernel<<<nb, 1024>>>(n);
    fill_kernel<<<gE, 256>>>(src, dst, e);

    // L1: GCN 128->32  (mm prescaled -> half; agg -> prescaled half h1p)
    mm_kernel<128, 32, 1><<<(n + 31) / 32, 128>>>(x, W1, t0h, n, nullptr, nullptr, nullptr, 0);
    gcn_agg32_L1<<<gW, 256>>>(t0h, b1, h1p, n);

    // L2: GCN 32->64, aggregate-first (agg in 32ch, then mm + bias + relu)
    agg32_L2<<<gW, 256>>>(h1p, z, n);
    mm_kernel<32, 64, 3><<<(n + 15) / 16, 128>>>(z, W2, ha, n, nullptr, nullptr, b2, 0);  // ha = h2

    // L3: GAT 64->64
    mm_kernel<64, 64, 2><<<(n + 15) / 16, 128>>>(ha, Wg, t0h, n, ats, atd, nullptr, 0);
    gat_agg<false><<<gW, 256>>>(t0h, bg, hb, nullptr, nullptr, 0, n);                     // hb = h3

    // L4: GCN 64->64 + residual
    mm_kernel<64, 64, 1><<<(n + 15) / 16, 128>>>(hb, W3, t0h, n, nullptr, nullptr, nullptr, 0);
    gcn_agg64h<<<gW, 256>>>(t0h, b3, hb, ha, n);                                          // ha = h4

    // L5: GAT 64->64 fused with final head
    mm_kernel<64, 64, 2><<<(n + 15) / 16, 128>>>(ha, Wg, t0h, n, ats, atd, nullptr, 4);
    gat_agg<true><<<gW, 256>>>(t0h, bg, out, Wl, bl, 4, n);
}

// round 14
// speedup vs baseline: 1.5052x; 1.4210x over previous
#include <cuda_runtime.h>
#include <cuda_fp16.h>

#define NN 100000
#define NE 1600000
#define FULL 0xffffffffu

typedef unsigned long long u64;

#define FMA_F32X2(d, a, b, c) \
    asm("fma.rn.f32x2 %0, %1, %2, %3;" : "=l"(d) : "l"(a), "l"(b), "l"(c))
#define UNPACK_F32X2(lo, hi, in) \
    asm("mov.b64 {%0, %1}, %2;" : "=f"(lo), "=f"(hi) : "l"(in))

// ---------------- scratch ----------------
__device__ int      g_cnt[NN];
__device__ int      g_roff[NN + 1];
__device__ int      g_woff[NN + 1];
__device__ int      g_csrc[NE];
__device__ int      g_bsum[128];
__device__ unsigned g_asmax[8];          // per-head global max of a_s, 2 GAT layers
__device__ float    g_dinv[NN];
__device__ float    g_as[NN * 4];
__device__ float    g_ad[NN * 4];
__device__ __half   g_t0h[NN * 64];      // pre-agg features (half)
__device__ __half   g_h1p[NN * 32];      // layer-1 output, dinv-prescaled (half)
__device__ float    g_z[NN * 32];        // layer-2 aggregated 32ch (fp32)
__device__ float    g_ha[NN * 64];
__device__ float    g_hb[NN * 64];

// ordered-float <-> unsigned encoding for atomicMax
__device__ __forceinline__ unsigned fenc(float f) {
    int i = __float_as_int(f);
    return (i >= 0) ? ((unsigned)i | 0x80000000u) : ~(unsigned)i;
}
__device__ __forceinline__ float fdec(unsigned k) {
    int i = (k & 0x80000000u) ? (int)(k & 0x7fffffffu) : ~(int)k;
    return __int_as_float(i);
}

// ---------------- CSR build ----------------
__global__ void deg_kernel(const int* __restrict__ dst, int e) {
    int i = blockIdx.x * blockDim.x + threadIdx.x;
    if (i < e) atomicAdd(&g_cnt[dst[i]], 1);
}

__global__ void scan1_kernel(int n) {
    __shared__ int wsum[32];
    int i = blockIdx.x * 1024 + threadIdx.x;
    int lane = threadIdx.x & 31, wid = threadIdx.x >> 5;
    int v = (i < n) ? g_cnt[i] : 0;
    if (i < n) g_dinv[i] = rsqrtf((float)(v + 1));
    int s = v;
#pragma unroll
    for (int o = 1; o < 32; o <<= 1) {
        int t = __shfl_up_sync(FULL, s, o);
        if (lane >= o) s += t;
    }
    if (lane == 31) wsum[wid] = s;
    __syncthreads();
    if (wid == 0) {
        int ws = wsum[lane];
#pragma unroll
        for (int o = 1; o < 32; o <<= 1) {
            int t = __shfl_up_sync(FULL, ws, o);
            if (lane >= o) ws += t;
        }
        wsum[lane] = ws;
    }
    __syncthreads();
    if (wid > 0) s += wsum[wid - 1];
    if (i < n) g_roff[i + 1] = s;
    if (i == 0) g_roff[0] = 0;
    if (threadIdx.x == 1023) g_bsum[blockIdx.x] = s;
}

__global__ void scan2_kernel(int nb) {
    __shared__ int wsum[4];
    int lane = threadIdx.x & 31, wid = threadIdx.x >> 5;
    int v = (threadIdx.x < nb) ? g_bsum[threadIdx.x] : 0;
    int s = v;
#pragma unroll
    for (int o = 1; o < 32; o <<= 1) {
        int t = __shfl_up_sync(FULL, s, o);
        if (lane >= o) s += t;
    }
    if (lane == 31) wsum[wid] = s;
    __syncthreads();
    int add = 0;
    for (int w = 0; w < wid; w++) add += wsum[w];
    s += add;
    if (threadIdx.x < nb) g_bsum[threadIdx.x] = s;
}

__global__ void scan3_kernel(int n) {
    int i = blockIdx.x * 1024 + threadIdx.x;
    if (blockIdx.x == 0 && threadIdx.x < 8) g_asmax[threadIdx.x] = 0u;
    if (i < n) {
        int add = (blockIdx.x > 0) ? g_bsum[blockIdx.x - 1] : 0;
        int val = g_roff[i + 1] + add;
        g_roff[i + 1] = val;
        g_woff[i + 1] = val;
        if (i == 0) g_woff[0] = 0;
    }
}

__global__ void fill_kernel(const int* __restrict__ src, const int* __restrict__ dst, int e) {
    int i = blockIdx.x * blockDim.x + threadIdx.x;
    if (i < e) {
        int d = dst[i];
        int p = atomicAdd(&g_woff[d], 1);
        g_csrc[p] = src[i];
    }
}

// ---------------- dense matmul (f32x2, duplicated-X smem), 2 rows/thread ----------------
// MODE 1: prescale by g_dinv, write half     (GCN pre-agg)
// MODE 2: write half + a_s/a_d + global max  (GAT pre-agg)
// MODE 3: +bias, relu, write fp32            (layer-2 post-agg)
template <int IN, int OUT, int MODE>
__global__ void __launch_bounds__(128) mm_kernel(const float* __restrict__ X,
                                                 const float* __restrict__ W,
                                                 void* __restrict__ Yv, int n,
                                                 const float* __restrict__ ats,
                                                 const float* __restrict__ atd,
                                                 const float* __restrict__ bias,
                                                 int lbase) {
    constexpr int TPR = OUT / 4;
    constexpr int NR  = 128 / TPR;
    constexpr int RPB = NR * 2;
    __shared__ __align__(16) float Ws[IN * OUT];
    __shared__ __align__(16) float2 Xs[RPB * IN];   // duplicated {x,x}
    __shared__ unsigned smax[4];

    for (int i = threadIdx.x; i < IN * OUT / 4; i += 128)
        ((float4*)Ws)[i] = ((const float4*)W)[i];
    if (MODE == 2 && threadIdx.x < 4) smax[threadIdx.x] = 0u;

    int row0 = blockIdx.x * RPB;
    for (int i = threadIdx.x; i < RPB * IN / 4; i += 128) {
        int r = i / (IN / 4);
        int k4 = i % (IN / 4);
        int row = row0 + r;
        float4 val = make_float4(0.f, 0.f, 0.f, 0.f);
        if (row < n) val = ((const float4*)(X + (size_t)row * IN))[k4];
        float2* xp = &Xs[r * IN + k4 * 4];
        xp[0] = make_float2(val.x, val.x);
        xp[1] = make_float2(val.y, val.y);
        xp[2] = make_float2(val.z, val.z);
        xp[3] = make_float2(val.w, val.w);
    }
    __syncthreads();

    int tr = threadIdx.x / TPR;
    int cg = threadIdx.x % TPR;
    int rA = 2 * tr, rB = 2 * tr + 1;

    u64 acc00 = 0, acc01 = 0, acc10 = 0, acc11 = 0;
    const ulonglong2* Ws2 = (const ulonglong2*)Ws;
    const u64* XA = (const u64*)&Xs[rA * IN];
    const u64* XB = (const u64*)&Xs[rB * IN];
#pragma unroll 16
    for (int k = 0; k < IN; k++) {
        u64 x0p = XA[k];
        u64 x1p = XB[k];
        ulonglong2 w = Ws2[k * TPR + cg];
        FMA_F32X2(acc00, w.x, x0p, acc00);
        FMA_F32X2(acc01, w.y, x0p, acc01);
        FMA_F32X2(acc10, w.x, x1p, acc10);
        FMA_F32X2(acc11, w.y, x1p, acc11);
    }

    float4 a0, a1;
    UNPACK_F32X2(a0.x, a0.y, acc00);
    UNPACK_F32X2(a0.z, a0.w, acc01);
    UNPACK_F32X2(a1.x, a1.y, acc10);
    UNPACK_F32X2(a1.z, a1.w, acc11);

    int rowA = row0 + rA, rowB = row0 + rB;

    if (MODE == 1) {
        if (rowA < n) {
            float s = g_dinv[rowA];
            a0.x *= s; a0.y *= s; a0.z *= s; a0.w *= s;
        }
        if (rowB < n) {
            float s = g_dinv[rowB];
            a1.x *= s; a1.y *= s; a1.z *= s; a1.w *= s;
        }
    }

    if (MODE == 1 || MODE == 2) {
        __half* Y = (__half*)Yv;
        if (rowA < n) {
            __half2 lo = __floats2half2_rn(a0.x, a0.y), hi = __floats2half2_rn(a0.z, a0.w);
            uint2 pk; pk.x = *(unsigned*)&lo; pk.y = *(unsigned*)&hi;
            *(uint2*)(Y + (size_t)rowA * OUT + cg * 4) = pk;
        }
        if (rowB < n) {
            __half2 lo = __floats2half2_rn(a1.x, a1.y), hi = __floats2half2_rn(a1.z, a1.w);
            uint2 pk; pk.x = *(unsigned*)&lo; pk.y = *(unsigned*)&hi;
            *(uint2*)(Y + (size_t)rowB * OUT + cg * 4) = pk;
        }
    } else {  // MODE 3
        float* Y = (float*)Yv;
        float4 b4 = ((const float4*)bias)[cg];
        a0.x = fmaxf(a0.x + b4.x, 0.f); a0.y = fmaxf(a0.y + b4.y, 0.f);
        a0.z = fmaxf(a0.z + b4.z, 0.f); a0.w = fmaxf(a0.w + b4.w, 0.f);
        a1.x = fmaxf(a1.x + b4.x, 0.f); a1.y = fmaxf(a1.y + b4.y, 0.f);
        a1.z = fmaxf(a1.z + b4.z, 0.f); a1.w = fmaxf(a1.w + b4.w, 0.f);
        if (rowA < n) ((float4*)(Y + (size_t)rowA * OUT))[cg] = a0;
        if (rowB < n) ((float4*)(Y + (size_t)rowB * OUT))[cg] = a1;
    }

    if (MODE == 2) {
        int head = cg >> 2;
        float4 av = ((const float4*)ats)[head * 4 + (cg & 3)];
        float4 dv = ((const float4*)atd)[head * 4 + (cg & 3)];
        float ps0 = a0.x * av.x + a0.y * av.y + a0.z * av.z + a0.w * av.w;
        float pd0 = a0.x * dv.x + a0.y * dv.y + a0.z * dv.z + a0.w * dv.w;
        float ps1 = a1.x * av.x + a1.y * av.y + a1.z * av.z + a1.w * av.w;
        float pd1 = a1.x * dv.x + a1.y * dv.y + a1.z * dv.z + a1.w * dv.w;
        ps0 += __shfl_down_sync(FULL, ps0, 2, 4); ps0 += __shfl_down_sync(FULL, ps0, 1, 4);
        pd0 += __shfl_down_sync(FULL, pd0, 2, 4); pd0 += __shfl_down_sync(FULL, pd0, 1, 4);
        ps1 += __shfl_down_sync(FULL, ps1, 2, 4); ps1 += __shfl_down_sync(FULL, ps1, 1, 4);
        pd1 += __shfl_down_sync(FULL, pd1, 2, 4); pd1 += __shfl_down_sync(FULL, pd1, 1, 4);
        if ((cg & 3) == 0) {
            if (rowA < n) {
                g_as[rowA * 4 + head] = ps0; g_ad[rowA * 4 + head] = pd0;
                atomicMax(&smax[head], fenc(ps0));
            }
            if (rowB < n) {
                g_as[rowB * 4 + head] = ps1; g_ad[rowB * 4 + head] = pd1;
                atomicMax(&smax[head], fenc(ps1));
            }
        }
        __syncthreads();
        if (threadIdx.x < 4) atomicMax(&g_asmax[lbase + threadIdx.x], smax[threadIdx.x]);
    }
}

// ---------------- 32ch GCN agg, unroll 8. L1: half out (prescaled); L2: fp32 out ----------------
template <int OUTMODE>   // 0: half prescaled out (needs bias+relu), 1: fp32 plain out
__global__ void __launch_bounds__(256) agg32(const __half* __restrict__ h,
                                             const float* __restrict__ bias,
                                             void* __restrict__ outv, int n) {
    int v = (blockIdx.x * blockDim.x + threadIdx.x) >> 5;
    int lane = threadIdx.x & 31;
    if (v >= n) return;
    float dv = g_dinv[v];
    float acc = __half2float(h[(size_t)v * 32 + lane]);
    int e0 = g_roff[v], e1 = g_roff[v + 1];
    int e = e0;
    for (; e + 8 <= e1; e += 8) {
        int u0 = g_csrc[e],     u1 = g_csrc[e + 1], u2 = g_csrc[e + 2], u3 = g_csrc[e + 3];
        int u4 = g_csrc[e + 4], u5 = g_csrc[e + 5], u6 = g_csrc[e + 6], u7 = g_csrc[e + 7];
        float p0 = __half2float(h[(size_t)u0 * 32 + lane]);
        float p1 = __half2float(h[(size_t)u1 * 32 + lane]);
        float p2 = __half2float(h[(size_t)u2 * 32 + lane]);
        float p3 = __half2float(h[(size_t)u3 * 32 + lane]);
        float p4 = __half2float(h[(size_t)u4 * 32 + lane]);
        float p5 = __half2float(h[(size_t)u5 * 32 + lane]);
        float p6 = __half2float(h[(size_t)u6 * 32 + lane]);
        float p7 = __half2float(h[(size_t)u7 * 32 + lane]);
        acc += ((p0 + p1) + (p2 + p3)) + ((p4 + p5) + (p6 + p7));
    }
    for (; e < e1; e++) acc += __half2float(h[(size_t)g_csrc[e] * 32 + lane]);
    if (OUTMODE == 0) {
        float o = fmaxf(dv * acc + bias[lane], 0.f);
        ((__half*)outv)[(size_t)v * 32 + lane] = __float2half(dv * o);
    } else {
        ((float*)outv)[(size_t)v * 32 + lane] = dv * acc;
    }
}

// ---------------- GCN 64ch agg: half in (prescaled), fp32 out + residual, unroll 8 ----------------
__global__ void __launch_bounds__(256) gcn_agg64h(const __half* __restrict__ h,
                                                  const float* __restrict__ bias,
                                                  const float* __restrict__ res,
                                                  float* __restrict__ out, int n) {
    int v = (blockIdx.x * blockDim.x + threadIdx.x) >> 5;
    int lane = threadIdx.x & 31;
    if (v >= n) return;
    const __half2* h2 = (const __half2*)h;
    float dv = g_dinv[v];
    float2 acc = __half22float2(h2[(size_t)v * 32 + lane]);
    int e0 = g_roff[v], e1 = g_roff[v + 1];
    int e = e0;
    for (; e + 8 <= e1; e += 8) {
        int u0 = g_csrc[e],     u1 = g_csrc[e + 1], u2 = g_csrc[e + 2], u3 = g_csrc[e + 3];
        int u4 = g_csrc[e + 4], u5 = g_csrc[e + 5], u6 = g_csrc[e + 6], u7 = g_csrc[e + 7];
        float2 p0 = __half22float2(h2[(size_t)u0 * 32 + lane]);
        float2 p1 = __half22float2(h2[(size_t)u1 * 32 + lane]);
        float2 p2 = __half22float2(h2[(size_t)u2 * 32 + lane]);
        float2 p3 = __half22float2(h2[(size_t)u3 * 32 + lane]);
        float2 p4 = __half22float2(h2[(size_t)u4 * 32 + lane]);
        float2 p5 = __half22float2(h2[(size_t)u5 * 32 + lane]);
        float2 p6 = __half22float2(h2[(size_t)u6 * 32 + lane]);
        float2 p7 = __half22float2(h2[(size_t)u7 * 32 + lane]);
        acc.x += ((p0.x + p1.x) + (p2.x + p3.x)) + ((p4.x + p5.x) + (p6.x + p7.x));
        acc.y += ((p0.y + p1.y) + (p2.y + p3.y)) + ((p4.y + p5.y) + (p6.y + p7.y));
    }
    for (; e < e1; e++) {
        float2 p = __half22float2(h2[(size_t)g_csrc[e] * 32 + lane]);
        acc.x += p.x; acc.y += p.y;
    }
    float2 b2 = ((const float2*)bias)[lane];
    float2 r2 = ((const float2*)res)[(size_t)v * 32 + lane];
    float2 o;
    o.x = fmaxf(dv * acc.x + b2.x, 0.f) + r2.x;
    o.y = fmaxf(dv * acc.y + b2.y, 0.f) + r2.y;
    ((float2*)out)[(size_t)v * 32 + lane] = o;
}

// ---------------- GAT ----------------
__device__ __forceinline__ float leakyr(float x) { return x > 0.f ? x : 0.2f * x; }
__device__ __forceinline__ float sel4(float4 v, int h) {
    float a = (h & 1) ? v.y : v.x;
    float b = (h & 1) ? v.w : v.z;
    return (h & 2) ? b : a;
}

template <bool FINAL>
__global__ void __launch_bounds__(256) gat_agg(const __half* __restrict__ hg,
                                               const float* __restrict__ bias,
                                               float* __restrict__ out,
                                               const float* __restrict__ Wl,
                                               const float* __restrict__ bl,
                                               int lbase, int n) {
    int v = (blockIdx.x * blockDim.x + threadIdx.x) >> 5;
    int lane = threadIdx.x & 31;
    if (v >= n) return;
    int hh = lane >> 3;
    const __half2* h2 = (const __half2*)hg;
    const float4* as4 = (const float4*)g_as;
    const float4* ad4p = (const float4*)g_ad;

    float4 asv = as4[v];
    float4 adv = ad4p[v];
    float advh = sel4(adv, hh);
    float mx = leakyr(fdec(g_asmax[lbase + hh]) + advh);   // global upper bound

    float pself = __expf(leakyr(sel4(asv, hh) + advh) - mx);
    float2 hv = __half22float2(h2[(size_t)v * 32 + lane]);
    float2 acc; acc.x = pself * hv.x; acc.y = pself * hv.y;
    float den = pself;

    int e0 = g_roff[v], e1 = g_roff[v + 1];
    int e = e0;
    for (; e + 4 <= e1; e += 4) {
        int u0 = g_csrc[e], u1 = g_csrc[e + 1], u2 = g_csrc[e + 2], u3 = g_csrc[e + 3];
        float4 au0 = as4[u0], au1 = as4[u1], au2 = as4[u2], au3 = as4[u3];
        float2 f0 = __half22float2(h2[(size_t)u0 * 32 + lane]);
        float2 f1 = __half22float2(h2[(size_t)u1 * 32 + lane]);
        float2 f2 = __half22float2(h2[(size_t)u2 * 32 + lane]);
        float2 f3 = __half22float2(h2[(size_t)u3 * 32 + lane]);
        float p0 = __expf(leakyr(sel4(au0, hh) + advh) - mx);
        float p1 = __expf(leakyr(sel4(au1, hh) + advh) - mx);
        float p2 = __expf(leakyr(sel4(au2, hh) + advh) - mx);
        float p3 = __expf(leakyr(sel4(au3, hh) + advh) - mx);
        acc.x += (p0 * f0.x + p1 * f1.x) + (p2 * f2.x + p3 * f3.x);
        acc.y += (p0 * f0.y + p1 * f1.y) + (p2 * f2.y + p3 * f3.y);
        den += (p0 + p1) + (p2 + p3);
    }
    for (; e < e1; e++) {
        int u = g_csrc[e];
        float4 au = as4[u];
        float p = __expf(leakyr(sel4(au, hh) + advh) - mx);
        float2 fu = __half22float2(h2[(size_t)u * 32 + lane]);
        acc.x += p * fu.x; acc.y += p * fu.y;
        den += p;
    }
    float inv = 1.f / den;
    float2 b2 = ((const float2*)bias)[lane];
    float2 o;
    o.x = fmaxf(acc.x * inv + b2.x, 0.f);
    o.y = fmaxf(acc.y * inv + b2.y, 0.f);

    if (FINAL) {
        float2 wl = ((const float2*)Wl)[lane];
        float p = o.x * wl.x + o.y * wl.y;
#pragma unroll
        for (int s = 16; s; s >>= 1) p += __shfl_xor_sync(FULL, p, s);
        if (lane == 0) out[v] = fmaxf(p + bl[0], 0.f);
    } else {
        ((float2*)out)[(size_t)v * 32 + lane] = o;
    }
}

// ---------------- launch ----------------
extern "C" void kernel_launch(void* const* d_in, const int* in_sizes, int n_in,
                              void* d_out, int out_size) {
    const float* x   = (const float*)d_in[0];
    const int*   ei  = (const int*)d_in[1];
    const float* W1  = (const float*)d_in[2];
    const float* b1  = (const float*)d_in[3];
    const float* W2  = (const float*)d_in[4];
    const float* b2  = (const float*)d_in[5];
    const float* W3  = (const float*)d_in[6];
    const float* b3  = (const float*)d_in[7];
    const float* Wg  = (const float*)d_in[8];
    const float* ats = (const float*)d_in[9];
    const float* atd = (const float*)d_in[10];
    const float* bg  = (const float*)d_in[11];
    const float* Wl  = (const float*)d_in[12];
    const float* bl  = (const float*)d_in[13];
    float* out = (float*)d_out;

    int n = in_sizes[0] / 128;
    int e = in_sizes[1] / 2;
    const int* src = ei;
    const int* dst = ei + e;

    void* p;
    int* cnt_ptr; cudaGetSymbolAddress(&p, g_cnt); cnt_ptr = (int*)p;
    __half *t0h, *h1p;
    float *z, *ha, *hb;
    cudaGetSymbolAddress(&p, g_t0h); t0h = (__half*)p;
    cudaGetSymbolAddress(&p, g_h1p); h1p = (__half*)p;
    cudaGetSymbolAddress(&p, g_z);   z   = (float*)p;
    cudaGetSymbolAddress(&p, g_ha);  ha  = (float*)p;
    cudaGetSymbolAddress(&p, g_hb);  hb  = (float*)p;

    int nb = (n + 1023) / 1024;
    int gE = (e + 255) / 256;
    int gW = (n * 32 + 255) / 256;

    // CSR build (also resets GAT global maxes in scan3)
    cudaMemsetAsync(cnt_ptr, 0, sizeof(int) * NN, 0);
    deg_kernel<<<gE, 256>>>(dst, e);
    scan1_kernel<<<nb, 1024>>>(n);
    scan2_kernel<<<1, 128>>>(nb);
    scan3_kernel<<<nb, 1024>>>(n);
    fill_kernel<<<gE, 256>>>(src, dst, e);

    // L1: GCN 128->32  (mm prescaled -> half; agg -> prescaled half h1p)
    mm_kernel<128, 32, 1><<<(n + 31) / 32, 128>>>(x, W1, t0h, n, nullptr, nullptr, nullptr, 0);
    agg32<0><<<gW, 256>>>(t0h, b1, h1p, n);

    // L2: GCN 32->64, aggregate-first (agg in 32ch, then mm + bias + relu)
    agg32<1><<<gW, 256>>>(h1p, nullptr, z, n);
    mm_kernel<32, 64, 3><<<(n + 15) / 16, 128>>>(z, W2, ha, n, nullptr, nullptr, b2, 0);  // ha = h2

    // L3: GAT 64->64
    mm_kernel<64, 64, 2><<<(n + 15) / 16, 128>>>(ha, Wg, t0h, n, ats, atd, nullptr, 0);
    gat_agg<false><<<gW, 256>>>(t0h, bg, hb, nullptr, nullptr, 0, n);                     // hb = h3

    // L4: GCN 64->64 + residual
    mm_kernel<64, 64, 1><<<(n + 15) / 16, 128>>>(hb, W3, t0h, n, nullptr, nullptr, nullptr, 0);
    gcn_agg64h<<<gW, 256>>>(t0h, b3, hb, ha, n);                                          // ha = h4

    // L5: GAT 64->64 fused with final head
    mm_kernel<64, 64, 2><<<(n + 15) / 16, 128>>>(ha, Wg, t0h, n, ats, atd, nullptr, 4);
    gat_agg<true><<<gW, 256>>>(t0h, bg, out, Wl, bl, 4, n);
}